// round 6
// baseline (speedup 1.0000x reference)
#include <cuda_runtime.h>
#include <cuda_bf16.h>
#include <math.h>

#define BINS  10
#define BLOCK 256
#define GRID  1184   // 148 SMs * 8

// Per-block partials {sum,cnt}, bin-major for coalesced last-block reads.
// Written unconditionally every launch -> no zeroing kernel needed.
__device__ float2 g_part[BINS * GRID];
__device__ unsigned int g_ticket;   // zero at load; last block resets each launch

__device__ __forceinline__ void process_elem(float p, float t, float w,
                                             float2* __restrict__ hist) {
    if (w > 0.0f) {
        // t in {0,1}: q = (t>0)? -p : p; then |sigmoid(p)-t| = sigmoid(q), bce = softplus(q)
        float q  = (t > 0.0f) ? -p : p;
        float aq = fabsf(q);
        float e  = __expf(-aq);                 // exp(-|q|) in (0,1]
        float r;                                 // approx 1/(1+e), only for binning
        asm("rcp.approx.f32 %0, %1;" : "=f"(r) : "f"(1.0f + e));
        float g  = (q >= 0.0f) ? r : e * r;     // sigmoid(q)
        int bin  = (int)(g * 10.0f);
        bin = bin > (BINS - 1) ? (BINS - 1) : bin;
        // bce independent of approx r: max(q,0) + log(1+e)
        float bce = fmaxf(q, 0.0f) + __logf(1.0f + e);
        float2 a = hist[bin * BLOCK];           // LDS.64, conflict-free ([bin][tid])
        a.x += bce;
        a.y += 1.0f;
        hist[bin * BLOCK] = a;                  // STS.64
    }
}

__global__ void __launch_bounds__(BLOCK)
ghm_main(const float* __restrict__ pred,
         const float* __restrict__ target,
         const float* __restrict__ lw,
         int n, float* __restrict__ out) {
    // Per-thread private histogram: [bin][tid] float2 -> conflict-free 64-bit access.
    __shared__ float2 s_hist[BINS * BLOCK];

    const int tid = threadIdx.x;
    float2* __restrict__ hist = s_hist + tid;   // per-thread column base
#pragma unroll
    for (int b = 0; b < BINS; b++)
        hist[b * BLOCK] = make_float2(0.0f, 0.0f);

    const int n4 = n >> 2;
    const float4* __restrict__ p4 = (const float4*)pred;
    const float4* __restrict__ t4 = (const float4*)target;
    const float4* __restrict__ w4 = (const float4*)lw;

    const int stride = GRID * BLOCK;
    for (int i = blockIdx.x * BLOCK + tid; i < n4; i += stride) {
        // Register-free MLP boost: stage i+2*stride into L2 while processing i.
        int ipf = i + 2 * stride;
        if (ipf < n4) {
            asm volatile("prefetch.global.L2 [%0];" :: "l"(p4 + ipf));
            asm volatile("prefetch.global.L2 [%0];" :: "l"(t4 + ipf));
            asm volatile("prefetch.global.L2 [%0];" :: "l"(w4 + ipf));
        }
        float4 p = p4[i];
        float4 t = t4[i];
        float4 w = w4[i];
        process_elem(p.x, t.x, w.x, hist);
        process_elem(p.y, t.y, w.y, hist);
        process_elem(p.z, t.z, w.z, hist);
        process_elem(p.w, t.w, w.w, hist);
    }
    // Scalar tail (n not multiple of 4) — block 0 only.
    if (blockIdx.x == 0) {
        for (int j = (n4 << 2) + tid; j < n; j += BLOCK)
            process_elem(pred[j], target[j], lw[j], hist);
    }

    __syncthreads();
    // Tree-reduce each bin's 256 partials.
    for (int s = BLOCK / 2; s > 0; s >>= 1) {
        if (tid < s) {
#pragma unroll
            for (int b = 0; b < BINS; b++) {
                float2 x = s_hist[b * BLOCK + tid];
                float2 y = s_hist[b * BLOCK + tid + s];
                s_hist[b * BLOCK + tid] = make_float2(x.x + y.x, x.y + y.y);
            }
        }
        __syncthreads();
    }
    if (tid < BINS) {
        g_part[tid * GRID + blockIdx.x] = s_hist[tid * BLOCK];  // cnt <= ~28K, fp32-exact
        __threadfence();   // only the 10 writer threads fence (release)
    }
    __syncthreads();

    // ---- last-block finalization ----
    __shared__ bool s_last;
    if (tid == 0) {
        unsigned int t = atomicAdd(&g_ticket, 1u);
        s_last = (t == GRID - 1u);
    }
    __syncthreads();
    if (!s_last) return;

    __shared__ double r_sum[BINS * (BLOCK / 32)];
    __shared__ double r_cnt[BINS * (BLOCK / 32)];
    const int lane = tid & 31, wid = tid >> 5;
    const int NW = BLOCK / 32;

#pragma unroll
    for (int b = 0; b < BINS; b++) {
        float fs = 0.0f, fc = 0.0f;
        // float4 = two consecutive float2 partials of the same bin (GRID is even).
        const float4* row = (const float4*)&g_part[b * GRID];
        for (int j = tid; j < GRID / 2; j += BLOCK) {
            float4 v = __ldcg(&row[j]);    // coalesced 16B, bypass stale L1
            fs += v.x + v.z;
            fc += v.y + v.w;               // sums of few small ints -> exact
        }
        double ds = (double)fs, dc = (double)fc;
#pragma unroll
        for (int o = 16; o > 0; o >>= 1) {
            ds += __shfl_down_sync(0xFFFFFFFFu, ds, o);
            dc += __shfl_down_sync(0xFFFFFFFFu, dc, o);
        }
        if (lane == 0) { r_sum[b * NW + wid] = ds; r_cnt[b * NW + wid] = dc; }
    }
    __syncthreads();

    if (tid == 0) {
        double acc = 0.0;
        int ne = 0;
#pragma unroll
        for (int b = 0; b < BINS; b++) {
            double s = 0.0, c = 0.0;
#pragma unroll
            for (int w = 0; w < NW; w++) { s += r_sum[b * NW + w]; c += r_cnt[b * NW + w]; }
            if (c > 0.0) { acc += s / c; ne++; }
        }
        float loss = (ne > 0) ? (float)(acc / (double)ne) : 0.0f;
        out[0] = loss * 1.0f;   // LOSS_WEIGHT
        g_ticket = 0u;          // reset for next graph replay
    }
}

extern "C" void kernel_launch(void* const* d_in, const int* in_sizes, int n_in,
                              void* d_out, int out_size) {
    const float* pred   = (const float*)d_in[0];
    const float* target = (const float*)d_in[1];
    const float* lw     = (const float*)d_in[2];
    float* out = (float*)d_out;
    int n = in_sizes[0];

    ghm_main<<<GRID, BLOCK>>>(pred, target, lw, n, out);
}

// round 7
// speedup vs baseline: 1.0665x; 1.0665x over previous
#include <cuda_runtime.h>
#include <cuda_bf16.h>
#include <math.h>

#define BINS  10
#define BLOCK 256
#define GRID  1184   // 148 SMs * 8 resident blocks

// Per-block partials, bin-major for coalesced last-block reads.
// Written unconditionally by every block every launch -> no zeroing needed.
__device__ float g_psum[BINS * GRID];
__device__ float g_pcnt[BINS * GRID];
__device__ unsigned int g_ticket;   // zero-init at load; last block resets each launch

// ---- R1-verbatim element path (fastest measured) ----
__device__ __forceinline__ void process_elem(float p, float t, float w,
                                             float* s_sum, float* s_cnt, int tid) {
    if (w > 0.0f) {
        float ap = fabsf(p);
        float e  = __expf(-ap);          // exp(-|p|), shared by sigmoid and log1p term
        float r  = __frcp_rn(1.0f + e);  // 1/(1+e)
        float s  = (p >= 0.0f) ? r : e * r;   // sigmoid(p)
        float g  = fabsf(s - t);
        int bin  = (int)(g * 10.0f);
        bin = bin > (BINS - 1) ? (BINS - 1) : bin;
        float bce = fmaxf(p, 0.0f) - p * t + __logf(1.0f + e);
        s_sum[bin * BLOCK + tid] += bce;
        s_cnt[bin * BLOCK + tid] += 1.0f;
    }
}

__global__ void __launch_bounds__(BLOCK)
ghm_main(const float* __restrict__ pred,
         const float* __restrict__ target,
         const float* __restrict__ lw,
         int n, float* __restrict__ out) {
    // Per-thread private histogram columns: [bin][tid] -> bank = tid%32, conflict-free.
    __shared__ float s_sum[BINS * BLOCK];
    __shared__ float s_cnt[BINS * BLOCK];

    const int tid = threadIdx.x;
#pragma unroll
    for (int b = 0; b < BINS; b++) {
        s_sum[b * BLOCK + tid] = 0.0f;
        s_cnt[b * BLOCK + tid] = 0.0f;
    }

    const int n4 = n >> 2;
    const float4* __restrict__ p4 = (const float4*)pred;
    const float4* __restrict__ t4 = (const float4*)target;
    const float4* __restrict__ w4 = (const float4*)lw;

    const int stride = GRID * BLOCK;
    for (int i = blockIdx.x * BLOCK + tid; i < n4; i += stride) {
        float4 p = p4[i];
        float4 t = t4[i];
        float4 w = w4[i];
        process_elem(p.x, t.x, w.x, s_sum, s_cnt, tid);
        process_elem(p.y, t.y, w.y, s_sum, s_cnt, tid);
        process_elem(p.z, t.z, w.z, s_sum, s_cnt, tid);
        process_elem(p.w, t.w, w.w, s_sum, s_cnt, tid);
    }
    // Scalar tail (n not multiple of 4) — block 0 only.
    if (blockIdx.x == 0) {
        for (int j = (n4 << 2) + tid; j < n; j += BLOCK)
            process_elem(pred[j], target[j], lw[j], s_sum, s_cnt, tid);
    }

    __syncthreads();
    // Tree-reduce each bin's 256 partials.
    for (int s = BLOCK / 2; s > 0; s >>= 1) {
        if (tid < s) {
#pragma unroll
            for (int b = 0; b < BINS; b++) {
                s_sum[b * BLOCK + tid] += s_sum[b * BLOCK + tid + s];
                s_cnt[b * BLOCK + tid] += s_cnt[b * BLOCK + tid + s];
            }
        }
        __syncthreads();
    }
    if (tid < BINS) {
        g_psum[tid * GRID + blockIdx.x] = s_sum[tid * BLOCK];
        g_pcnt[tid * GRID + blockIdx.x] = s_cnt[tid * BLOCK];  // <= ~28K, fp32-exact
        __threadfence();   // release, writers only
    }
    __syncthreads();

    // ---- last-block finalization (no extra kernels) ----
    __shared__ bool s_last;
    if (tid == 0) {
        unsigned int t = atomicAdd(&g_ticket, 1u);
        s_last = (t == GRID - 1u);
    }
    __syncthreads();
    if (!s_last) return;

    __shared__ double r_sum[BINS * (BLOCK / 32)];
    __shared__ double r_cnt[BINS * (BLOCK / 32)];
    const int lane = tid & 31, wid = tid >> 5;
    const int NW = BLOCK / 32;

#pragma unroll
    for (int b = 0; b < BINS; b++) {
        float fs = 0.0f, fc = 0.0f;
        const float4* srow = (const float4*)&g_psum[b * GRID];
        const float4* crow = (const float4*)&g_pcnt[b * GRID];
        for (int j = tid; j < GRID / 4; j += BLOCK) {
            float4 vs = __ldcg(&srow[j]);   // coalesced 16B, bypass stale L1
            float4 vc = __ldcg(&crow[j]);
            fs += (vs.x + vs.y) + (vs.z + vs.w);
            fc += (vc.x + vc.y) + (vc.z + vc.w);  // sums of few small ints -> exact
        }
        double ds = (double)fs, dc = (double)fc;
#pragma unroll
        for (int o = 16; o > 0; o >>= 1) {
            ds += __shfl_down_sync(0xFFFFFFFFu, ds, o);
            dc += __shfl_down_sync(0xFFFFFFFFu, dc, o);
        }
        if (lane == 0) { r_sum[b * NW + wid] = ds; r_cnt[b * NW + wid] = dc; }
    }
    __syncthreads();

    if (tid == 0) {
        double acc = 0.0;
        int ne = 0;
#pragma unroll
        for (int b = 0; b < BINS; b++) {
            double s = 0.0, c = 0.0;
#pragma unroll
            for (int w = 0; w < NW; w++) { s += r_sum[b * NW + w]; c += r_cnt[b * NW + w]; }
            if (c > 0.0) { acc += s / c; ne++; }
        }
        float loss = (ne > 0) ? (float)(acc / (double)ne) : 0.0f;
        out[0] = loss * 1.0f;   // LOSS_WEIGHT
        g_ticket = 0u;          // reset for next graph replay
    }
}

extern "C" void kernel_launch(void* const* d_in, const int* in_sizes, int n_in,
                              void* d_out, int out_size) {
    const float* pred   = (const float*)d_in[0];
    const float* target = (const float*)d_in[1];
    const float* lw     = (const float*)d_in[2];
    float* out = (float*)d_out;
    int n = in_sizes[0];

    ghm_main<<<GRID, BLOCK>>>(pred, target, lw, n, out);
}